// round 1
// baseline (speedup 1.0000x reference)
#include <cuda_runtime.h>
#include <cstdint>
#include <cstddef>

// ---------------------------------------------------------------- constants
#define B_   8
#define NL_  64
#define NT_  512
#define H_   128
#define E_   2048
#define M_   4096
#define P_TOT (B_*NL_*NT_)          // 262144 pairs

// output layout: tuple flattened in return order, float32
#define OUT_PI 0
#define OUT_SG (P_TOT*10)           // 2621440
#define OUT_MU (P_TOT*20)           // 5242880
#define OUT_CB (P_TOT*30)           // 7864320
#define OUT_AT (OUT_CB + P_TOT)     // 8126464  (512*18)
#define OUT_BT (OUT_AT + 512*18)    // 8135680  (2048*5)
#define OUT_CD (OUT_BT + E_*5)      // 8145920  (4096)
#define OUT_CM (OUT_CD + M_)        // 8150016  (262144)

// ---------------------------------------------------------------- scratch
__device__ float g_Lh[512*128];     // lig @ W_top, BN-scaled, bias folded
__device__ float g_ThT[128*4096];   // (pro @ W_bot)*s, TRANSPOSED [h][ti]
__device__ float g_Ls[512*128];     // selector lig part (bias folded)
__device__ float g_Ts[4096*128];    // selector pro part
__device__ float g_sM[128], g_cM[128], g_sS[128], g_cS[128];

// ---------------------------------------------------------------- helpers
__device__ __forceinline__ float eluf(float x) {
    return x > 0.f ? x : (__expf(x) - 1.f);
}

__device__ __forceinline__ float2 ffma2(float2 a, float2 b, float2 c) {
    float2 d;
    asm("fma.rn.f32x2 %0, %1, %2, %3;"
        : "=l"(reinterpret_cast<unsigned long long&>(d))
        : "l"(reinterpret_cast<unsigned long long&>(a)),
          "l"(reinterpret_cast<unsigned long long&>(b)),
          "l"(reinterpret_cast<unsigned long long&>(c)));
    return d;
}

// ---------------------------------------------------------------- prep: fold BN
// s[h] = g[h]*rsqrt(v[h]+eps); c[h] = (b[h]-m[h])*s[h] + be[h]
__global__ void prep_scale(const float* __restrict__ g, const float* __restrict__ be,
                           const float* __restrict__ m, const float* __restrict__ v,
                           const float* __restrict__ b,
                           float* __restrict__ s_out, float* __restrict__ c_out) {
    int h = threadIdx.x;
    float s = g[h] * rsqrtf(v[h] + 1e-5f);
    s_out[h] = s;
    c_out[h] = (b[h] - m[h]) * s + be[h];
}

// ---------------------------------------------------------------- generic K=128 GEMM
// C[r][c] = (sum_k A[r][k] * W[(wrow0+k)*ldw + c]) * scale[c] + bias[c]
// M multiple of 64. N arbitrary (bounds-checked). Optional transposed store.
__global__ void gemm_k128(const float* __restrict__ A,
                          const float* __restrict__ W, int ldw, int wrow0, int N,
                          const float* __restrict__ scale, const float* __restrict__ bias,
                          float* __restrict__ C, int ldc, int transC) {
    __shared__ float As[64][68];
    __shared__ float Ws[64][68];
    int tid = threadIdx.x;
    int tx = tid & 15, ty = tid >> 4;
    int r0 = blockIdx.y * 64, c0 = blockIdx.x * 64;
    float acc[4][4] = {};

    for (int kc = 0; kc < 128; kc += 64) {
        for (int q = tid; q < 64*16; q += 256) {
            int r = q >> 4, k4 = q & 15;
            float4 val = *(const float4*)(A + (size_t)(r0 + r) * 128 + kc + k4 * 4);
            *(float4*)&As[r][k4 * 4] = val;
        }
        for (int q = tid; q < 64*64; q += 256) {
            int k = q >> 6, c = q & 63;
            float w = 0.f;
            if (c0 + c < N) w = W[(size_t)(wrow0 + kc + k) * ldw + c0 + c];
            Ws[k][c] = w;
        }
        __syncthreads();
        #pragma unroll 8
        for (int k = 0; k < 64; k++) {
            float a_[4];
            #pragma unroll
            for (int d = 0; d < 4; d++) a_[d] = As[ty * 4 + d][k];
            float4 w4 = *(const float4*)&Ws[k][tx * 4];
            float wv[4] = {w4.x, w4.y, w4.z, w4.w};
            #pragma unroll
            for (int d = 0; d < 4; d++)
                #pragma unroll
                for (int e = 0; e < 4; e++)
                    acc[d][e] = fmaf(a_[d], wv[e], acc[d][e]);
        }
        __syncthreads();
    }

    #pragma unroll
    for (int d = 0; d < 4; d++) {
        int r = r0 + ty * 4 + d;
        #pragma unroll
        for (int e = 0; e < 4; e++) {
            int c = c0 + tx * 4 + e;
            if (c < N) {
                float v = acc[d][e];
                if (scale) v *= scale[c];
                if (bias)  v += bias[c];
                if (transC) C[(size_t)c * ldc + r] = v;
                else        C[(size_t)r * ldc + c] = v;
            }
        }
    }
}

// ---------------------------------------------------------------- main fused pair kernel
// Per block: tile of 8 lig rows x 128 pro cols (1024 pairs). 256 threads:
// thread = (il 0..7, jt 0..31), each owns 4 consecutive j (packed f32x2 math).
#define SMEM_MAIN ((128*132 + 8*128) * 4 + 128*30*8)   // 102400 B

__global__ void __launch_bounds__(256, 1)
pair_kernel(const float* __restrict__ Lh, const float* __restrict__ ThT,
            const float* __restrict__ pi_w, const float* __restrict__ pi_b,
            const float* __restrict__ sg_w, const float* __restrict__ sg_b,
            const float* __restrict__ mu_w, const float* __restrict__ mu_b,
            float* __restrict__ out) {
    extern __shared__ float sm[];
    float*  Th_s = sm;                       // [h][j] stride 132 (16B-aligned rows)
    float*  L_s  = sm + 128 * 132;           // [il][h] stride 128
    float2* Wp   = (float2*)(L_s + 8 * 128); // [h][k] duplicated-pair weights

    int tid = threadIdx.x;
    int blk = blockIdx.x;                    // 256 blocks: b(8) x ig(8) x jg(4)
    int jg = blk & 3;
    int ig = (blk >> 2) & 7;
    int b  = blk >> 5;
    int ti_base = b * 512 + jg * 128;
    int li_base = b * 64 + ig * 8;

    // load Th tile (pre-transposed in gmem -> conflict-free everywhere)
    for (int q = tid; q < 128 * 32; q += 256) {
        int h = q >> 5, j4 = q & 31;
        float4 v = *(const float4*)(ThT + (size_t)h * 4096 + ti_base + j4 * 4);
        *(float4*)&Th_s[h * 132 + j4 * 4] = v;
    }
    // load L rows
    for (int q = tid; q < 8 * 32; q += 256) {
        int r = q >> 5, k4 = q & 31;
        *(float4*)&L_s[r * 128 + k4 * 4] =
            *(const float4*)(Lh + (size_t)(li_base + r) * 128 + k4 * 4);
    }
    // pack head weights: Wp[h*30+k] = {w,w}; k: 0-9 pi, 10-19 sg, 20-29 mu
    for (int q = tid; q < 128 * 30; q += 256) {
        int h = q / 30, k = q - h * 30;
        float w = (k < 10) ? pi_w[h * 10 + k]
                : (k < 20) ? sg_w[h * 10 + k - 10]
                           : mu_w[h * 10 + k - 20];
        Wp[q] = make_float2(w, w);
    }
    __syncthreads();

    int il = tid >> 5, jt = tid & 31;
    const float* Lrow = L_s + il * 128;

    float2 a01[30], a23[30];
    #pragma unroll
    for (int k = 0; k < 30; k++) { a01[k] = make_float2(0.f, 0.f); a23[k] = make_float2(0.f, 0.f); }

    #pragma unroll 2
    for (int h = 0; h < 128; h++) {
        float lv = Lrow[h];
        float4 t = *(const float4*)&Th_s[h * 132 + jt * 4];
        float c0 = eluf(lv + t.x);
        float c1 = eluf(lv + t.y);
        float c2 = eluf(lv + t.z);
        float c3 = eluf(lv + t.w);
        float2 p01 = make_float2(c0, c1);
        float2 p23 = make_float2(c2, c3);
        const float2* wr = Wp + h * 30;
        #pragma unroll
        for (int k = 0; k < 30; k++) {
            float2 w = wr[k];
            a01[k] = ffma2(p01, w, a01[k]);
            a23[k] = ffma2(p23, w, a23[k]);
        }
    }

    // biases
    float pib[10], sgb[10], mub[10];
    #pragma unroll
    for (int k = 0; k < 10; k++) {
        pib[k] = __ldg(pi_b + k); sgb[k] = __ldg(sg_b + k); mub[k] = __ldg(mu_b + k);
    }

    int p0 = (li_base + il) * 512 + jg * 128 + jt * 4;   // first pair index
    float obuf[40];

    // ---- pi (softmax) ----
    #pragma unroll
    for (int jj = 0; jj < 4; jj++) {
        float v[10];
        #pragma unroll
        for (int k = 0; k < 10; k++) {
            float x = (jj == 0) ? a01[k].x : (jj == 1) ? a01[k].y
                    : (jj == 2) ? a23[k].x : a23[k].y;
            v[k] = x + pib[k];
        }
        float mx = v[0];
        #pragma unroll
        for (int k = 1; k < 10; k++) mx = fmaxf(mx, v[k]);
        float s = 0.f;
        #pragma unroll
        for (int k = 0; k < 10; k++) { v[k] = __expf(v[k] - mx); s += v[k]; }
        float inv = 1.0f / s;
        #pragma unroll
        for (int k = 0; k < 10; k++) obuf[jj * 10 + k] = v[k] * inv;
    }
    {
        float4* dst = (float4*)(out + OUT_PI + (size_t)p0 * 10);
        #pragma unroll
        for (int q = 0; q < 10; q++) dst[q] = ((float4*)obuf)[q];
    }
    // ---- sigma = elu(x)+1.1 ----
    #pragma unroll
    for (int jj = 0; jj < 4; jj++)
        #pragma unroll
        for (int k = 0; k < 10; k++) {
            float x = (jj == 0) ? a01[10 + k].x : (jj == 1) ? a01[10 + k].y
                    : (jj == 2) ? a23[10 + k].x : a23[10 + k].y;
            obuf[jj * 10 + k] = eluf(x + sgb[k]) + 1.1f;
        }
    {
        float4* dst = (float4*)(out + OUT_SG + (size_t)p0 * 10);
        #pragma unroll
        for (int q = 0; q < 10; q++) dst[q] = ((float4*)obuf)[q];
    }
    // ---- mu = elu(x)+1.0 ----
    #pragma unroll
    for (int jj = 0; jj < 4; jj++)
        #pragma unroll
        for (int k = 0; k < 10; k++) {
            float x = (jj == 0) ? a01[20 + k].x : (jj == 1) ? a01[20 + k].y
                    : (jj == 2) ? a23[20 + k].x : a23[20 + k].y;
            obuf[jj * 10 + k] = eluf(x + mub[k]) + 1.0f;
        }
    {
        float4* dst = (float4*)(out + OUT_MU + (size_t)p0 * 10);
        #pragma unroll
        for (int q = 0; q < 10; q++) dst[q] = ((float4*)obuf)[q];
    }
}

// ---------------------------------------------------------------- donor selector
__global__ void donar_kernel(const int* __restrict__ donar_idx,
                             const float* __restrict__ Ls, const float* __restrict__ Ts,
                             const float* __restrict__ w2, const float* __restrict__ b2,
                             float* __restrict__ out) {
    int m = blockIdx.x * 8 + (threadIdx.x >> 5);
    int lane = threadIdx.x & 31;
    int p = donar_idx[m];
    int li = p / 512;                            // = b*64 + i
    int ti = (p >> 15) * 512 + (p & 511);        // = b*512 + j
    float acc = 0.f;
    #pragma unroll
    for (int hq = 0; hq < 4; hq++) {
        int h = lane + hq * 32;
        float x = Ls[(size_t)li * 128 + h] + Ts[(size_t)ti * 128 + h];
        acc = fmaf(eluf(x), __ldg(w2 + h), acc);
    }
    #pragma unroll
    for (int o = 16; o; o >>= 1) acc += __shfl_xor_sync(0xffffffffu, acc, o);
    if (lane == 0) out[m] = 1.f / (1.f + __expf(-(acc + __ldg(b2))));
}

// ---------------------------------------------------------------- bond types
__global__ void bond_kernel(const int* __restrict__ ei, const float* __restrict__ lig,
                            const float* __restrict__ w, const float* __restrict__ bb,
                            float* __restrict__ out) {
    int t = blockIdx.x * blockDim.x + threadIdx.x;
    if (t >= E_ * 5) return;
    int e = t / 5, c = t - e * 5;
    int e0 = ei[e], e1 = ei[E_ + e];
    float acc = bb[c];
    const float* r0 = lig + (size_t)e0 * 128;
    const float* r1 = lig + (size_t)e1 * 128;
    #pragma unroll 4
    for (int k = 0; k < 128; k++) acc = fmaf(r0[k], __ldg(w + k * 5 + c), acc);
    #pragma unroll 4
    for (int k = 0; k < 128; k++) acc = fmaf(r1[k], __ldg(w + (128 + k) * 5 + c), acc);
    out[t] = acc;
}

// ---------------------------------------------------------------- C_batch + C_mask
__global__ void fill_kernel(float* __restrict__ out) {
    int q = blockIdx.x * blockDim.x + threadIdx.x;
    if (q < P_TOT) {
        out[OUT_CB + q] = (float)(q >> 15);   // q / (64*512)
        out[OUT_CM + q] = 1.0f;               // masks all-True by construction
    }
}

// ---------------------------------------------------------------- launch
extern "C" void kernel_launch(void* const* d_in, const int* in_sizes, int n_in,
                              void* d_out, int out_size) {
    const float* lig_s  = (const float*)d_in[0];
    const float* pro_s  = (const float*)d_in[1];
    const int*   donar  = (const int*)d_in[4];
    const int*   eidx   = (const int*)d_in[5];
    const float* mlp_w  = (const float*)d_in[6];
    const float* mlp_b  = (const float*)d_in[7];
    const float* mlp_g  = (const float*)d_in[8];
    const float* mlp_be = (const float*)d_in[9];
    const float* mlp_m  = (const float*)d_in[10];
    const float* mlp_v  = (const float*)d_in[11];
    const float* sel_w1 = (const float*)d_in[12];
    const float* sel_b1 = (const float*)d_in[13];
    const float* sel_g  = (const float*)d_in[14];
    const float* sel_be = (const float*)d_in[15];
    const float* sel_m  = (const float*)d_in[16];
    const float* sel_v  = (const float*)d_in[17];
    const float* sel_w2 = (const float*)d_in[18];
    const float* sel_b2 = (const float*)d_in[19];
    const float* pi_w   = (const float*)d_in[20];
    const float* pi_b   = (const float*)d_in[21];
    const float* sg_w   = (const float*)d_in[22];
    const float* sg_b   = (const float*)d_in[23];
    const float* mu_w   = (const float*)d_in[24];
    const float* mu_b   = (const float*)d_in[25];
    const float* at_w   = (const float*)d_in[26];
    const float* at_b   = (const float*)d_in[27];
    const float* bt_w   = (const float*)d_in[28];
    const float* bt_b   = (const float*)d_in[29];
    float* out = (float*)d_out;

    float *Lh, *ThT, *Ls, *Ts, *sM, *cM, *sS, *cS;
    cudaGetSymbolAddress((void**)&Lh,  g_Lh);
    cudaGetSymbolAddress((void**)&ThT, g_ThT);
    cudaGetSymbolAddress((void**)&Ls,  g_Ls);
    cudaGetSymbolAddress((void**)&Ts,  g_Ts);
    cudaGetSymbolAddress((void**)&sM,  g_sM);
    cudaGetSymbolAddress((void**)&cM,  g_cM);
    cudaGetSymbolAddress((void**)&sS,  g_sS);
    cudaGetSymbolAddress((void**)&cS,  g_cS);

    cudaFuncSetAttribute((const void*)pair_kernel,
                         cudaFuncAttributeMaxDynamicSharedMemorySize, SMEM_MAIN);

    // fold BN into per-column scale/bias
    prep_scale<<<1, 128>>>(mlp_g, mlp_be, mlp_m, mlp_v, mlp_b, sM, cM);
    prep_scale<<<1, 128>>>(sel_g, sel_be, sel_m, sel_v, sel_b1, sS, cS);

    // small GEMMs (K=128)
    gemm_k128<<<dim3(2, 8),  256>>>(lig_s, mlp_w,  128, 0,   128, sM, cM,     Lh,  128,  0);
    gemm_k128<<<dim3(2, 8),  256>>>(lig_s, sel_w1, 128, 0,   128, sS, cS,     Ls,  128,  0);
    gemm_k128<<<dim3(1, 8),  256>>>(lig_s, at_w,   18,  0,   18,  nullptr, at_b, out + OUT_AT, 18, 0);
    gemm_k128<<<dim3(2, 64), 256>>>(pro_s, mlp_w,  128, 128, 128, sM, nullptr, ThT, 4096, 1);
    gemm_k128<<<dim3(2, 64), 256>>>(pro_s, sel_w1, 128, 128, 128, sS, nullptr, Ts,  128,  0);

    // fused pairwise MDN head
    pair_kernel<<<256, 256, SMEM_MAIN>>>(Lh, ThT, pi_w, pi_b, sg_w, sg_b, mu_w, mu_b, out);

    // small outputs
    donar_kernel<<<M_ / 8, 256>>>(donar, Ls, Ts, sel_w2, sel_b2, out + OUT_CD);
    bond_kernel<<<(E_ * 5 + 255) / 256, 256>>>(eidx, lig_s, bt_w, bt_b, out + OUT_BT);
    fill_kernel<<<(P_TOT + 255) / 256, 256>>>(out);
}

// round 2
// speedup vs baseline: 1.3985x; 1.3985x over previous
#include <cuda_runtime.h>
#include <cstdint>
#include <cstddef>

// ---------------------------------------------------------------- constants
#define B_   8
#define NL_  64
#define NT_  512
#define H_   128
#define E_   2048
#define M_   4096
#define P_TOT (B_*NL_*NT_)          // 262144 pairs

// output layout: tuple flattened in return order, float32
#define OUT_PI 0
#define OUT_SG (P_TOT*10)
#define OUT_MU (P_TOT*20)
#define OUT_CB (P_TOT*30)
#define OUT_AT (OUT_CB + P_TOT)
#define OUT_BT (OUT_AT + 512*18)
#define OUT_CD (OUT_BT + E_*5)
#define OUT_CM (OUT_CD + M_)

// ---------------------------------------------------------------- scratch
__device__ float g_Lh[512*128];     // lig @ W_top, BN folded
__device__ float g_ThT[128*4096];   // (pro @ W_bot)*s, TRANSPOSED [h][ti]
__device__ float g_Ls[512*128];     // selector lig part
__device__ float g_Ts[4096*128];    // selector pro part

// ---------------------------------------------------------------- helpers
__device__ __forceinline__ float eluf(float x) {
    return x > 0.f ? x : (__expf(x) - 1.f);
}
__device__ __forceinline__ float2 ffma2(float2 a, float2 b, float2 c) {
    float2 d;
    asm("fma.rn.f32x2 %0, %1, %2, %3;"
        : "=l"(reinterpret_cast<unsigned long long&>(d))
        : "l"(reinterpret_cast<unsigned long long&>(a)),
          "l"(reinterpret_cast<unsigned long long&>(b)),
          "l"(reinterpret_cast<unsigned long long&>(c)));
    return d;
}

// ================================================================ FRONT kernel
// One launch, block-range dispatch:
//  [0,16)    lig@mlp_w  -> Lh   (BN fold + bias)
//  [16,32)   lig@sel_w1 -> Ls   (BN fold + bias)
//  [32,40)   lig@at_w   -> out.AT (bias only, N=18)
//  [40,168)  pro@mlp_w[128:]*sM -> ThT (transposed store)
//  [168,296) pro@sel_w1[128:]*sS -> Ts
//  [296,336) bond types
//  [336,352) C_batch + C_mask fill
#define FRONT_BLOCKS 352

// GEMM tile: 64 rows x 64 cols, K=128, 256 threads, thread = 4x4 micro-tile.
// mode 0: lig (scale s + full bias (b-m)*s+be), 1: pro (scale only), 2: bias-only
__device__ __forceinline__ void gemm64(
    const float* __restrict__ A, const float* __restrict__ W, int ldw, int wrow0, int N,
    int r0, int c0, int mode,
    const float* __restrict__ g, const float* __restrict__ be,
    const float* __restrict__ m, const float* __restrict__ v,
    const float* __restrict__ lb,
    float* __restrict__ C, int ldc, int transC,
    float (*Ast)[68], float (*Ws)[68]) {

    int tid = threadIdx.x;
    int tx = tid & 15, ty = tid >> 4;
    float acc[4][4] = {};

    for (int kc = 0; kc < 128; kc += 64) {
        // A chunk, stored transposed: Ast[k][r]
        #pragma unroll
        for (int q = tid; q < 64 * 16; q += 256) {
            int r = q >> 4, k4 = q & 15;
            float4 val = *(const float4*)(A + (size_t)(r0 + r) * 128 + kc + k4 * 4);
            Ast[k4 * 4 + 0][r] = val.x;
            Ast[k4 * 4 + 1][r] = val.y;
            Ast[k4 * 4 + 2][r] = val.z;
            Ast[k4 * 4 + 3][r] = val.w;
        }
        // W chunk: Ws[k][c]
        #pragma unroll
        for (int q = tid; q < 64 * 64; q += 256) {
            int k = q >> 6, c = q & 63;
            float w = 0.f;
            if (c0 + c < N) w = W[(size_t)(wrow0 + kc + k) * ldw + c0 + c];
            Ws[k][c] = w;
        }
        __syncthreads();
        #pragma unroll 16
        for (int k = 0; k < 64; k++) {
            float4 a4 = *(const float4*)&Ast[k][ty * 4];
            float4 w4 = *(const float4*)&Ws[k][tx * 4];
            float av[4] = {a4.x, a4.y, a4.z, a4.w};
            float wv[4] = {w4.x, w4.y, w4.z, w4.w};
            #pragma unroll
            for (int d = 0; d < 4; d++)
                #pragma unroll
                for (int e = 0; e < 4; e++)
                    acc[d][e] = fmaf(av[d], wv[e], acc[d][e]);
        }
        __syncthreads();
    }

    #pragma unroll
    for (int e = 0; e < 4; e++) {
        int c = c0 + tx * 4 + e;
        if (c >= N) continue;
        float s = 1.f, cb = 0.f;
        if (mode == 0) {
            s = g[c] * rsqrtf(v[c] + 1e-5f);
            cb = (lb[c] - m[c]) * s + be[c];
        } else if (mode == 1) {
            s = g[c] * rsqrtf(v[c] + 1e-5f);
        } else {
            cb = lb[c];
        }
        #pragma unroll
        for (int d = 0; d < 4; d++) {
            int r = r0 + ty * 4 + d;
            float val = acc[d][e] * s + cb;
            if (transC) C[(size_t)c * ldc + r] = val;
            else        C[(size_t)r * ldc + c] = val;
        }
    }
}

__global__ void __launch_bounds__(256)
front_kernel(const float* __restrict__ lig_s, const float* __restrict__ pro_s,
             const int* __restrict__ eidx,
             const float* __restrict__ mlp_w, const float* __restrict__ mlp_b,
             const float* __restrict__ mlp_g, const float* __restrict__ mlp_be,
             const float* __restrict__ mlp_m, const float* __restrict__ mlp_v,
             const float* __restrict__ sel_w1, const float* __restrict__ sel_b1,
             const float* __restrict__ sel_g, const float* __restrict__ sel_be,
             const float* __restrict__ sel_m, const float* __restrict__ sel_v,
             const float* __restrict__ at_w, const float* __restrict__ at_b,
             const float* __restrict__ bt_w, const float* __restrict__ bt_b,
             float* __restrict__ Lh, float* __restrict__ ThT,
             float* __restrict__ Ls, float* __restrict__ Ts,
             float* __restrict__ out) {
    __shared__ float Ast[64][68];
    __shared__ float Ws[64][68];
    int blk = blockIdx.x;
    int tid = threadIdx.x;

    if (blk < 16) {            // lig @ mlp_w -> Lh
        int i = blk;
        gemm64(lig_s, mlp_w, 128, 0, 128, (i >> 1) * 64, (i & 1) * 64, 0,
               mlp_g, mlp_be, mlp_m, mlp_v, mlp_b, Lh, 128, 0, Ast, Ws);
    } else if (blk < 32) {     // lig @ sel_w1 -> Ls
        int i = blk - 16;
        gemm64(lig_s, sel_w1, 128, 0, 128, (i >> 1) * 64, (i & 1) * 64, 0,
               sel_g, sel_be, sel_m, sel_v, sel_b1, Ls, 128, 0, Ast, Ws);
    } else if (blk < 40) {     // lig @ at_w -> out.AT
        int i = blk - 32;
        gemm64(lig_s, at_w, 18, 0, 18, i * 64, 0, 2,
               nullptr, nullptr, nullptr, nullptr, at_b, out + OUT_AT, 18, 0, Ast, Ws);
    } else if (blk < 168) {    // pro @ mlp_w[128:] -> ThT (transposed)
        int i = blk - 40;
        gemm64(pro_s, mlp_w, 128, 128, 128, (i >> 1) * 64, (i & 1) * 64, 1,
               mlp_g, nullptr, nullptr, mlp_v, nullptr, ThT, 4096, 1, Ast, Ws);
    } else if (blk < 296) {    // pro @ sel_w1[128:] -> Ts
        int i = blk - 168;
        gemm64(pro_s, sel_w1, 128, 128, 128, (i >> 1) * 64, (i & 1) * 64, 1,
               sel_g, nullptr, nullptr, sel_v, nullptr, Ts, 128, 0, Ast, Ws);
    } else if (blk < 336) {    // bond types
        int t = (blk - 296) * 256 + tid;
        if (t < E_ * 5) {
            int e = t / 5, c = t - e * 5;
            int e0 = eidx[e], e1 = eidx[E_ + e];
            float acc = bt_b[c];
            const float* r0 = lig_s + (size_t)e0 * 128;
            const float* r1 = lig_s + (size_t)e1 * 128;
            #pragma unroll 4
            for (int k = 0; k < 128; k++) acc = fmaf(r0[k], __ldg(bt_w + k * 5 + c), acc);
            #pragma unroll 4
            for (int k = 0; k < 128; k++) acc = fmaf(r1[k], __ldg(bt_w + (128 + k) * 5 + c), acc);
            out[OUT_BT + t] = acc;
        }
    } else {                   // C_batch + C_mask (float4 writes)
        int base = (blk - 336) * 4096;       // 16 blocks x 4096 float4 = 262144 floats
        float4* cb = (float4*)(out + OUT_CB);
        float4* cm = (float4*)(out + OUT_CM);
        const float4 ones = make_float4(1.f, 1.f, 1.f, 1.f);
        #pragma unroll
        for (int it = 0; it < 16; it++) {
            int q = base + it * 256 + tid;   // float4 index
            float b = (float)((q * 4) >> 15);
            cb[q] = make_float4(b, b, b, b);
            cm[q] = ones;
        }
    }
}

// ================================================================ BACK kernel
// blocks [0,256): fused pairwise MDN head; [256,272): donor selector
#define SMEM_MAIN ((128*132 + 8*128) * 4 + 128*30*8)   // 102400 B
#define BACK_BLOCKS 272

__global__ void __launch_bounds__(256, 1)
back_kernel(const float* __restrict__ Lh, const float* __restrict__ ThT,
            const float* __restrict__ Ls, const float* __restrict__ Ts,
            const float* __restrict__ pi_w, const float* __restrict__ pi_b,
            const float* __restrict__ sg_w, const float* __restrict__ sg_b,
            const float* __restrict__ mu_w, const float* __restrict__ mu_b,
            const int* __restrict__ donar_idx,
            const float* __restrict__ sel_w2, const float* __restrict__ sel_b2,
            float* __restrict__ out) {
    int tid = threadIdx.x;
    int blk = blockIdx.x;

    if (blk >= 256) {
        // ---------------- donor selector: 16 blocks x 256 m each ----------------
        int w = tid >> 5, lane = tid & 31;
        int mbase = (blk - 256) * 256 + w;
        float w2v[4];
        #pragma unroll
        for (int hq = 0; hq < 4; hq++) w2v[hq] = __ldg(sel_w2 + lane + hq * 32);
        float b2 = __ldg(sel_b2);
        for (int it = 0; it < 32; it++) {
            int mm = mbase + it * 8;
            int p = donar_idx[mm];
            int li = p / 512;
            int ti = (p >> 15) * 512 + (p & 511);
            float acc = 0.f;
            #pragma unroll
            for (int hq = 0; hq < 4; hq++) {
                int h = lane + hq * 32;
                float x = Ls[(size_t)li * 128 + h] + Ts[(size_t)ti * 128 + h];
                acc = fmaf(eluf(x), w2v[hq], acc);
            }
            #pragma unroll
            for (int o = 16; o; o >>= 1) acc += __shfl_xor_sync(0xffffffffu, acc, o);
            if (lane == 0) out[OUT_CD + mm] = 1.f / (1.f + __expf(-(acc + b2)));
        }
        return;
    }

    // ---------------- pairwise MDN: tile 8 lig x 128 pro ----------------
    extern __shared__ float sm[];
    float*  Th_s = sm;                       // [h][j] stride 132
    float*  L_s  = sm + 128 * 132;           // [il][h] stride 128
    float2* Wp   = (float2*)(L_s + 8 * 128); // [h][k] duplicated-pair weights

    int jg = blk & 3;
    int ig = (blk >> 2) & 7;
    int b  = blk >> 5;
    int ti_base = b * 512 + jg * 128;
    int li_base = b * 64 + ig * 8;

    for (int q = tid; q < 128 * 32; q += 256) {
        int h = q >> 5, j4 = q & 31;
        float4 v = *(const float4*)(ThT + (size_t)h * 4096 + ti_base + j4 * 4);
        *(float4*)&Th_s[h * 132 + j4 * 4] = v;
    }
    for (int q = tid; q < 8 * 32; q += 256) {
        int r = q >> 5, k4 = q & 31;
        *(float4*)&L_s[r * 128 + k4 * 4] =
            *(const float4*)(Lh + (size_t)(li_base + r) * 128 + k4 * 4);
    }
    for (int q = tid; q < 128 * 30; q += 256) {
        int h = q / 30, k = q - h * 30;
        float w = (k < 10) ? pi_w[h * 10 + k]
                : (k < 20) ? sg_w[h * 10 + k - 10]
                           : mu_w[h * 10 + k - 20];
        Wp[q] = make_float2(w, w);
    }
    __syncthreads();

    int il = tid >> 5, jt = tid & 31;
    const float* Lrow = L_s + il * 128;

    float2 a01[30], a23[30];
    #pragma unroll
    for (int k = 0; k < 30; k++) { a01[k] = make_float2(0.f, 0.f); a23[k] = make_float2(0.f, 0.f); }

    #pragma unroll 2
    for (int h = 0; h < 128; h++) {
        float lv = Lrow[h];
        float4 t = *(const float4*)&Th_s[h * 132 + jt * 4];
        float2 p01 = make_float2(eluf(lv + t.x), eluf(lv + t.y));
        float2 p23 = make_float2(eluf(lv + t.z), eluf(lv + t.w));
        const float2* wr = Wp + h * 30;
        #pragma unroll
        for (int k = 0; k < 30; k++) {
            float2 w = wr[k];
            a01[k] = ffma2(p01, w, a01[k]);
            a23[k] = ffma2(p23, w, a23[k]);
        }
    }

    float pib[10], sgb[10], mub[10];
    #pragma unroll
    for (int k = 0; k < 10; k++) {
        pib[k] = __ldg(pi_b + k); sgb[k] = __ldg(sg_b + k); mub[k] = __ldg(mu_b + k);
    }

    int p0 = (li_base + il) * 512 + jg * 128 + jt * 4;
    float obuf[40];

    // pi (softmax)
    #pragma unroll
    for (int jj = 0; jj < 4; jj++) {
        float v[10];
        #pragma unroll
        for (int k = 0; k < 10; k++) {
            float x = (jj == 0) ? a01[k].x : (jj == 1) ? a01[k].y
                    : (jj == 2) ? a23[k].x : a23[k].y;
            v[k] = x + pib[k];
        }
        float mx = v[0];
        #pragma unroll
        for (int k = 1; k < 10; k++) mx = fmaxf(mx, v[k]);
        float s = 0.f;
        #pragma unroll
        for (int k = 0; k < 10; k++) { v[k] = __expf(v[k] - mx); s += v[k]; }
        float inv = 1.0f / s;
        #pragma unroll
        for (int k = 0; k < 10; k++) obuf[jj * 10 + k] = v[k] * inv;
    }
    {
        float4* dst = (float4*)(out + OUT_PI + (size_t)p0 * 10);
        #pragma unroll
        for (int q = 0; q < 10; q++) dst[q] = ((float4*)obuf)[q];
    }
    // sigma
    #pragma unroll
    for (int jj = 0; jj < 4; jj++)
        #pragma unroll
        for (int k = 0; k < 10; k++) {
            float x = (jj == 0) ? a01[10 + k].x : (jj == 1) ? a01[10 + k].y
                    : (jj == 2) ? a23[10 + k].x : a23[10 + k].y;
            obuf[jj * 10 + k] = eluf(x + sgb[k]) + 1.1f;
        }
    {
        float4* dst = (float4*)(out + OUT_SG + (size_t)p0 * 10);
        #pragma unroll
        for (int q = 0; q < 10; q++) dst[q] = ((float4*)obuf)[q];
    }
    // mu
    #pragma unroll
    for (int jj = 0; jj < 4; jj++)
        #pragma unroll
        for (int k = 0; k < 10; k++) {
            float x = (jj == 0) ? a01[20 + k].x : (jj == 1) ? a01[20 + k].y
                    : (jj == 2) ? a23[20 + k].x : a23[20 + k].y;
            obuf[jj * 10 + k] = eluf(x + mub[k]) + 1.0f;
        }
    {
        float4* dst = (float4*)(out + OUT_MU + (size_t)p0 * 10);
        #pragma unroll
        for (int q = 0; q < 10; q++) dst[q] = ((float4*)obuf)[q];
    }
}

// ================================================================ launch
extern "C" void kernel_launch(void* const* d_in, const int* in_sizes, int n_in,
                              void* d_out, int out_size) {
    const float* lig_s  = (const float*)d_in[0];
    const float* pro_s  = (const float*)d_in[1];
    const int*   donar  = (const int*)d_in[4];
    const int*   eidx   = (const int*)d_in[5];
    const float* mlp_w  = (const float*)d_in[6];
    const float* mlp_b  = (const float*)d_in[7];
    const float* mlp_g  = (const float*)d_in[8];
    const float* mlp_be = (const float*)d_in[9];
    const float* mlp_m  = (const float*)d_in[10];
    const float* mlp_v  = (const float*)d_in[11];
    const float* sel_w1 = (const float*)d_in[12];
    const float* sel_b1 = (const float*)d_in[13];
    const float* sel_g  = (const float*)d_in[14];
    const float* sel_be = (const float*)d_in[15];
    const float* sel_m  = (const float*)d_in[16];
    const float* sel_v  = (const float*)d_in[17];
    const float* sel_w2 = (const float*)d_in[18];
    const float* sel_b2 = (const float*)d_in[19];
    const float* pi_w   = (const float*)d_in[20];
    const float* pi_b   = (const float*)d_in[21];
    const float* sg_w   = (const float*)d_in[22];
    const float* sg_b   = (const float*)d_in[23];
    const float* mu_w   = (const float*)d_in[24];
    const float* mu_b   = (const float*)d_in[25];
    const float* at_w   = (const float*)d_in[26];
    const float* at_b   = (const float*)d_in[27];
    const float* bt_w   = (const float*)d_in[28];
    const float* bt_b   = (const float*)d_in[29];
    float* out = (float*)d_out;

    float *Lh, *ThT, *Ls, *Ts;
    cudaGetSymbolAddress((void**)&Lh,  g_Lh);
    cudaGetSymbolAddress((void**)&ThT, g_ThT);
    cudaGetSymbolAddress((void**)&Ls,  g_Ls);
    cudaGetSymbolAddress((void**)&Ts,  g_Ts);

    cudaFuncSetAttribute((const void*)back_kernel,
                         cudaFuncAttributeMaxDynamicSharedMemorySize, SMEM_MAIN);

    front_kernel<<<FRONT_BLOCKS, 256>>>(
        lig_s, pro_s, eidx,
        mlp_w, mlp_b, mlp_g, mlp_be, mlp_m, mlp_v,
        sel_w1, sel_b1, sel_g, sel_be, sel_m, sel_v,
        at_w, at_b, bt_w, bt_b,
        Lh, ThT, Ls, Ts, out);

    back_kernel<<<BACK_BLOCKS, 256, SMEM_MAIN>>>(
        Lh, ThT, Ls, Ts,
        pi_w, pi_b, sg_w, sg_b, mu_w, mu_b,
        donar, sel_w2, sel_b2, out);
}